// round 5
// baseline (speedup 1.0000x reference)
#include <cuda_runtime.h>
#include <cstdint>

#define N_NODES 100000
#define N_EDGES 800000
#define IN_DIM 128
#define HID_DIM 256
#define OUT_DIM 40

// ---------------- scratch (device globals; no allocation allowed) ----------------
__device__ int   g_is64;
__device__ int   g_eidx[2 * N_EDGES];            // decoded edge index (src | dst)
__device__ int   g_cnt[N_NODES];
__device__ int   g_rowptr[N_NODES + 1];
__device__ int   g_cursor[N_NODES];
__device__ int   g_perm[N_EDGES];
__device__ float g_agg[(size_t)N_NODES * 256];   // layer1: stride 128; layer2: stride 256
__device__ float g_h[(size_t)N_NODES * 256];

// ---------------- small helpers ----------------
__device__ __forceinline__ float4 f4add(float4 a, float4 b) {
    a.x += b.x; a.y += b.y; a.z += b.z; a.w += b.w; return a;
}
__device__ __forceinline__ float4 f4scale(float4 a, float s) {
    a.x *= s; a.y *= s; a.z *= s; a.w *= s; return a;
}

// ---------------- edge-index dtype probe + decode ----------------
// If the buffer is int64 (little-endian), every value is in [0, N_NODES), so the
// high 32-bit word of each 8-byte pair is 0. If it's int32, the odd int32
// positions are random node ids -> 512 consecutive zeros is impossible.
// Only reads the first 4 KB, which is in-bounds for either dtype.
__global__ void k_probe(const int* __restrict__ buf) {
    __shared__ int ok;
    if (threadIdx.x == 0) ok = 1;
    __syncthreads();
    int i = threadIdx.x;                 // 512 threads, pairs 0..511
    int lo = buf[2 * i];
    int hi = buf[2 * i + 1];
    if (!(hi == 0 && lo >= 0 && lo < N_NODES)) atomicAnd(&ok, 0);
    __syncthreads();
    if (threadIdx.x == 0) g_is64 = ok;
}

__global__ void k_decode(const void* __restrict__ buf) {
    int e = blockIdx.x * blockDim.x + threadIdx.x;
    if (e >= 2 * N_EDGES) return;
    int v;
    if (g_is64) v = (int)((const long long*)buf)[e];   // 8-byte path only when valid
    else        v = ((const int*)buf)[e];
    // clamp defensively: guarantees no OOB downstream regardless of input
    v = v < 0 ? 0 : (v >= N_NODES ? N_NODES - 1 : v);
    g_eidx[e] = v;
}

// ---------------- CSR construction ----------------
__global__ void k_zero_cnt() {
    int i = blockIdx.x * blockDim.x + threadIdx.x;
    if (i < N_NODES) g_cnt[i] = 0;
}

__global__ void k_hist() {
    int e = blockIdx.x * blockDim.x + threadIdx.x;
    if (e < N_EDGES) {
        int d = g_eidx[N_EDGES + e];
        atomicAdd(&g_cnt[d], 1);
    }
}

// single-block exclusive scan over g_cnt -> g_rowptr, g_cursor
__global__ void k_scan() {
    const int T = 1024;
    const int CH = (N_NODES + T - 1) / T;   // 98
    int t = threadIdx.x;
    int beg = t * CH;
    int end = beg + CH; if (end > N_NODES) end = N_NODES;
    int s = 0;
    for (int i = beg; i < end; i++) s += g_cnt[i];

    __shared__ int ps[T];
    ps[t] = s;
    __syncthreads();
    for (int off = 1; off < T; off <<= 1) {
        int v = 0;
        if (t >= off) v = ps[t - off];
        __syncthreads();
        ps[t] += v;
        __syncthreads();
    }
    int run = ps[t] - s;  // exclusive prefix for this chunk
    for (int i = beg; i < end; i++) {
        g_rowptr[i] = run;
        g_cursor[i] = run;
        run += g_cnt[i];
    }
    if (t == 0) g_rowptr[N_NODES] = N_EDGES;
}

__global__ void k_scatter() {
    int e = blockIdx.x * blockDim.x + threadIdx.x;
    if (e < N_EDGES) {
        int s = g_eidx[e];
        int d = g_eidx[N_EDGES + e];
        int pos = atomicAdd(&g_cursor[d], 1);
        g_perm[pos] = s;
    }
}

// ---------------- mean aggregation: one warp per node, no atomics ----------------
template <int D>
__global__ void __launch_bounds__(256) k_agg(const float* __restrict__ feat,
                                             float* __restrict__ out) {
    int warp = (blockIdx.x * blockDim.x + threadIdx.x) >> 5;
    if (warp >= N_NODES) return;
    int lane = threadIdx.x & 31;

    int beg = g_rowptr[warp];
    int end = g_rowptr[warp + 1];

    float4 a0 = make_float4(0.f, 0.f, 0.f, 0.f);
    float4 a1 = make_float4(0.f, 0.f, 0.f, 0.f);
    for (int e = beg; e < end; e++) {
        int s = g_perm[e];
        const float4* row = (const float4*)(feat + (size_t)s * D);
        a0 = f4add(a0, row[lane]);
        if (D == 256) a1 = f4add(a1, row[lane + 32]);
    }
    int deg = end - beg;
    float inv = 1.0f / (float)(deg > 0 ? deg : 1);
    float4* o = (float4*)(out + (size_t)warp * D);
    o[lane] = f4scale(a0, inv);
    if (D == 256) o[lane + 32] = f4scale(a1, inv);
}

// ---------------- fused SAGE GEMM:  C = op( (Aagg)@Wl + b + (Ax)@Wr ) ----------------
template <int K, int NTOT, bool RELU>
__global__ void __launch_bounds__(256) k_gemm(const float* __restrict__ Aagg,
                                              const float* __restrict__ Ax,
                                              const float* __restrict__ Wl,
                                              const float* __restrict__ Wr,
                                              const float* __restrict__ bias,
                                              float* __restrict__ C) {
    constexpr int BM = 64, NC = 64, KB = 32;
    __shared__ float sAg[BM][KB + 1];
    __shared__ float sAx[BM][KB + 1];
    __shared__ float sWl[KB][NC];
    __shared__ float sWr[KB][NC];

    int tid = threadIdx.x;
    int mBase = blockIdx.x * BM;
    int tx = tid & 15, ty = tid >> 4;
    int r0 = ty * 4, c0 = tx * 4;
    int lr = tid >> 3, lc = tid & 7;     // A tile loader: 32 rows x 8 float4-cols
    int wn = tid & 63, wk0 = tid >> 6;   // W tile loader: col wn, rows wk0 + 4*i

    for (int ncb = 0; ncb < NTOT; ncb += NC) {
        float acc[4][4];
        #pragma unroll
        for (int i = 0; i < 4; i++)
            #pragma unroll
            for (int j = 0; j < 4; j++) acc[i][j] = 0.f;

        for (int kb = 0; kb < K; kb += KB) {
            #pragma unroll
            for (int rr = 0; rr < BM; rr += 32) {
                int m = mBase + lr + rr;
                float4 va = make_float4(0.f, 0.f, 0.f, 0.f);
                float4 vx = va;
                if (m < N_NODES) {
                    va = *(const float4*)(Aagg + (size_t)m * K + kb + lc * 4);
                    vx = *(const float4*)(Ax   + (size_t)m * K + kb + lc * 4);
                }
                sAg[lr + rr][lc * 4 + 0] = va.x;
                sAg[lr + rr][lc * 4 + 1] = va.y;
                sAg[lr + rr][lc * 4 + 2] = va.z;
                sAg[lr + rr][lc * 4 + 3] = va.w;
                sAx[lr + rr][lc * 4 + 0] = vx.x;
                sAx[lr + rr][lc * 4 + 1] = vx.y;
                sAx[lr + rr][lc * 4 + 2] = vx.z;
                sAx[lr + rr][lc * 4 + 3] = vx.w;
            }
            #pragma unroll
            for (int kk = wk0; kk < KB; kk += 4) {
                int n = ncb + wn;
                float vl = 0.f, vr = 0.f;
                if (n < NTOT) {
                    vl = Wl[(size_t)(kb + kk) * NTOT + n];
                    vr = Wr[(size_t)(kb + kk) * NTOT + n];
                }
                sWl[kk][wn] = vl;
                sWr[kk][wn] = vr;
            }
            __syncthreads();

            #pragma unroll
            for (int k = 0; k < KB; k++) {
                float4 wl  = *(const float4*)&sWl[k][c0];
                float4 wr4 = *(const float4*)&sWr[k][c0];
                #pragma unroll
                for (int i = 0; i < 4; i++) {
                    float ag = sAg[r0 + i][k];
                    float ax = sAx[r0 + i][k];
                    acc[i][0] += ag * wl.x + ax * wr4.x;
                    acc[i][1] += ag * wl.y + ax * wr4.y;
                    acc[i][2] += ag * wl.z + ax * wr4.z;
                    acc[i][3] += ag * wl.w + ax * wr4.w;
                }
            }
            __syncthreads();
        }

        #pragma unroll
        for (int i = 0; i < 4; i++) {
            int m = mBase + r0 + i;
            if (m >= N_NODES) continue;
            #pragma unroll
            for (int j = 0; j < 4; j++) {
                int n = ncb + c0 + j;
                if (n >= NTOT) continue;
                float v = acc[i][j] + bias[n];
                if (RELU) v = fmaxf(v, 0.f);
                C[(size_t)m * NTOT + n] = v;
            }
        }
    }
}

// ---------------- launch ----------------
extern "C" void kernel_launch(void* const* d_in, const int* in_sizes, int n_in,
                              void* d_out, int out_size) {
    const float* x   = (const float*)d_in[0];
    const void*  ei  = d_in[1];                  // int32 or int64 — probed on device
    const float* W1l = (const float*)d_in[2];
    const float* b1  = (const float*)d_in[3];
    const float* W1r = (const float*)d_in[4];
    const float* W2l = (const float*)d_in[5];
    const float* b2  = (const float*)d_in[6];
    const float* W2r = (const float*)d_in[7];
    float* out = (float*)d_out;

    float* agg = nullptr; float* h = nullptr;
    cudaGetSymbolAddress((void**)&agg, g_agg);
    cudaGetSymbolAddress((void**)&h, g_h);

    const int TB = 256;

    // edge-index decode (dtype-agnostic)
    k_probe<<<1, 512>>>((const int*)ei);
    k_decode<<<(2 * N_EDGES + TB - 1) / TB, TB>>>(ei);

    // CSR build
    k_zero_cnt<<<(N_NODES + TB - 1) / TB, TB>>>();
    k_hist<<<(N_EDGES + TB - 1) / TB, TB>>>();
    k_scan<<<1, 1024>>>();
    k_scatter<<<(N_EDGES + TB - 1) / TB, TB>>>();

    // layer 1
    int aggBlocks = (N_NODES * 32 + TB - 1) / TB;
    k_agg<IN_DIM><<<aggBlocks, TB>>>(x, agg);
    int gemmBlocks = (N_NODES + 63) / 64;
    k_gemm<IN_DIM, HID_DIM, true><<<gemmBlocks, TB>>>(agg, x, W1l, W1r, b1, h);

    // layer 2
    k_agg<HID_DIM><<<aggBlocks, TB>>>(h, agg);
    k_gemm<HID_DIM, OUT_DIM, false><<<gemmBlocks, TB>>>(agg, h, W2l, W2r, b2, out);
}